// round 7
// baseline (speedup 1.0000x reference)
#include <cuda_runtime.h>

// ---------------- problem constants (fixed for this dataset) ----------------
#define Zl    384
#define MBr   46
#define DEGc  7
#define NBc   68
#define BEe   (MBr*DEGc)      // 322 base edges
#define NLD   (NBc*Zl)        // 26112 variable nodes
#define MCK   (MBr*Zl)        // 17664 check nodes
#define EDG   (BEe*Zl)        // 123648 edges
#define BATCH 128
#define B8    64              // batch in float2 units
#define KI    8448            // info bits out
#define NIN   25344           // received LLRs per batch row
#define NITER 20
#define LLRMAX 20.0f

// ---------------- static device scratch (no allocations allowed) ------------
// Single in-place edge message buffer: holds m_vc before k_cn, m_cv after.
// Footprint: 63.3 + 13.4 + 13.4 = ~90MB  -> resident in 126MB L2.
__device__ float2   g_msg[EDG*B8];      // edge messages (in-place)  63.3MB
__device__ float2   g_x[NLD*B8];        // final VN totals           13.4MB
__device__ float2   g_lch[NLD*B8];      // channel LLR (-clip)       13.4MB
__device__ unsigned g_bec[BEe];         // per base-edge: (c<<10)|shift
__device__ unsigned g_colptr[NBc+1];    // CSR over base columns
__device__ unsigned g_colent[BEe];      // (base_edge<<10)|shift

// ---------------- graph decode + CSR build (once per launch) ----------------
__global__ void k_build(const int* __restrict__ col) {
    int t = threadIdx.x;
    if (t < BEe) {
        int val = col[t * Zl];          // i=0 edge of this base-edge block
        g_bec[t] = ((unsigned)(val / Zl) << 10) | (unsigned)(val % Zl);
    }
    __syncthreads();
    if (t == 0) {
        unsigned cnt[NBc];
        for (int c = 0; c < NBc; c++) cnt[c] = 0;
        for (int e = 0; e < BEe; e++) cnt[g_bec[e] >> 10]++;
        unsigned run = 0;
        for (int c = 0; c < NBc; c++) { g_colptr[c] = run; run += cnt[c]; }
        g_colptr[NBc] = run;
        unsigned pos[NBc];
        for (int c = 0; c < NBc; c++) pos[c] = 0;
        for (int e = 0; e < BEe; e++) {
            unsigned c = g_bec[e] >> 10;
            g_colent[g_colptr[c] + pos[c]++] = ((unsigned)e << 10) | (g_bec[e] & 1023u);
        }
    }
}

// zero the punctured region of g_lch (first 2*Z variable nodes)
__global__ void k_zero() {
    int t = blockIdx.x * blockDim.x + threadIdx.x;   // 384*256 = 98304 = 768*128
    ((float*)g_lch)[t] = 0.0f;
}

// transpose + clip + negate channel LLRs: lch[(768+n)*128+b] = -clip(llr[b*NIN+n])
__global__ void k_lch(const float* __restrict__ llr) {
    __shared__ float tile[32][33];
    int n0 = blockIdx.x * 32, b0 = blockIdx.y * 32;
    int tx = threadIdx.x, ty = threadIdx.y;          // block (32, 8)
    float* lch = (float*)g_lch;
#pragma unroll
    for (int k = 0; k < 4; k++)
        tile[ty + k*8][tx] = llr[(size_t)(b0 + ty + k*8) * NIN + (n0 + tx)];
    __syncthreads();
#pragma unroll
    for (int k = 0; k < 4; k++) {
        float v = tile[tx][ty + k*8];
        v = fminf(fmaxf(v, -LLRMAX), LLRMAX);
        lch[(size_t)(768 + n0 + ty + k*8) * BATCH + (b0 + tx)] = -v;
    }
}

// ---------------- check-node update (min-sum, exclude-self) -----------------
// Branchless. Tie handling matches reference first-argmin exactly: on a tie
// m2 == m1, so (mag==m1 ? m2 : m1) gives the same value either way.
#define CNCOMP(F)                                                              \
    {                                                                          \
        float m1 = fabsf(v[0].F), m2 = 1e30f;                                  \
        unsigned par = __float_as_uint(v[0].F);                                \
        _Pragma("unroll")                                                      \
        for (int d = 1; d < DEGc; d++) {                                       \
            float mag = fabsf(v[d].F);                                         \
            m2 = fminf(m2, fmaxf(m1, mag));                                    \
            m1 = fminf(m1, mag);                                               \
            par ^= __float_as_uint(v[d].F);                                    \
        }                                                                      \
        par &= 0x80000000u;                                                    \
        _Pragma("unroll")                                                      \
        for (int d = 0; d < DEGc; d++) {                                       \
            unsigned bits = __float_as_uint(v[d].F);                           \
            float mag = fabsf(v[d].F);                                         \
            float sel = (mag == m1) ? m2 : m1;                                 \
            unsigned s = (par ^ bits) & 0x80000000u;                           \
            v[d].F = __uint_as_float(__float_as_uint(sel) | s);                \
        }                                                                      \
    }

template<bool FIRST>
__global__ void __launch_bounds__(256, 8) k_cn() {
    int tid = blockIdx.x * 256 + threadIdx.x;    // MCK*B8 = 1130496 = 4416*256
    int b8 = tid & 63;                           // batch float2 slot
    int m  = tid >> 6;                           // check index (warp-uniform pair)
    int r  = m / Zl;
    int i  = m - r * Zl;
    int beb  = r * DEGc;
    int base = (beb * Zl + i) * B8 + b8;

    float2 v[DEGc];
    if (FIRST) {
        // iteration 0: m_cv == 0 so m_vc == lch[col]; gather channel LLRs
#pragma unroll
        for (int d = 0; d < DEGc; d++) {
            unsigned u = g_bec[beb + d];
            int c  = (int)(u >> 10);
            int sh = (int)(u & 1023u);
            int iv = i + sh; if (iv >= Zl) iv -= Zl;
            v[d] = __ldg(&g_lch[(c * Zl + iv) * B8 + b8]);
        }
    } else {
        // steady state: m_vc stored contiguously (in place) by the VN kernel
#pragma unroll
        for (int d = 0; d < DEGc; d++)
            v[d] = g_msg[base + d * (Zl * B8)];
    }

    CNCOMP(x) CNCOMP(y)

    // in-place overwrite: buffer now holds m_cv
#pragma unroll
    for (int d = 0; d < DEGc; d++)
        g_msg[base + d * (Zl * B8)] = v[d];
}

// ---------------- variable-node update: m_vc = acc - m_cv, in place ---------
template<bool LAST>
__global__ void __launch_bounds__(256, 8) k_vn() {
    int tid = blockIdx.x * 256 + threadIdx.x;    // NLD*B8 = 1671168 = 6528*256
    int b8 = tid & 63;
    int v  = tid >> 6;
    int c  = v / Zl;
    int i  = v - c * Zl;
    float2 acc = g_lch[v * B8 + b8];
    unsigned j0 = g_colptr[c], j1 = g_colptr[c + 1];
    // pass 1: accumulate total (coalesced 256B per edge per warp)
    for (unsigned j = j0; j < j1; j++) {
        unsigned u = g_colent[j];
        int be = (int)(u >> 10);
        int sh = (int)(u & 1023u);
        int ic = i - sh; if (ic < 0) ic += Zl;
        float2 t = __ldg(&g_msg[(be * Zl + ic) * B8 + b8]);
        acc.x += t.x; acc.y += t.y;
    }
    if (LAST) {
        g_x[v * B8 + b8] = acc;
    } else {
        // pass 2: reload (L1-hot) and overwrite with extrinsic VN->CN messages
        for (unsigned j = j0; j < j1; j++) {
            unsigned u = g_colent[j];
            int be = (int)(u >> 10);
            int sh = (int)(u & 1023u);
            int ic = i - sh; if (ic < 0) ic += Zl;
            int idx = (be * Zl + ic) * B8 + b8;
            float2 t = __ldg(&g_msg[idx]);
            g_msg[idx] = make_float2(acc.x - t.x, acc.y - t.y);
        }
    }
}

// ---------------- output: out[b*K+n] = -x[n*128+b], n<K ---------------------
__global__ void k_out(float* __restrict__ out) {
    __shared__ float tile[32][33];
    const float* xf = (const float*)g_x;
    int n0 = blockIdx.x * 32, b0 = blockIdx.y * 32;
    int tx = threadIdx.x, ty = threadIdx.y;      // block (32, 8)
#pragma unroll
    for (int k = 0; k < 4; k++)
        tile[ty + k*8][tx] = xf[(size_t)(n0 + ty + k*8) * BATCH + (b0 + tx)];
    __syncthreads();
#pragma unroll
    for (int k = 0; k < 4; k++)
        out[(size_t)(b0 + ty + k*8) * KI + (n0 + tx)] = -tile[tx][ty + k*8];
}

// ---------------- launch ----------------------------------------------------
extern "C" void kernel_launch(void* const* d_in, const int* in_sizes, int n_in,
                              void* d_out, int out_size) {
    const float* llr = (const float*)d_in[0];
    const int*   col = (const int*)d_in[2];

    k_build<<<1, 512>>>(col);
    k_zero<<<384, 256>>>();
    {
        dim3 g(NIN / 32, BATCH / 32), b(32, 8);
        k_lch<<<g, b>>>(llr);
    }
    k_cn<true><<<(MCK * B8) / 256, 256>>>();
    k_vn<false><<<(NLD * B8) / 256, 256>>>();
    for (int it = 1; it < NITER - 1; it++) {
        k_cn<false><<<(MCK * B8) / 256, 256>>>();
        k_vn<false><<<(NLD * B8) / 256, 256>>>();
    }
    k_cn<false><<<(MCK * B8) / 256, 256>>>();
    k_vn<true><<<(NLD * B8) / 256, 256>>>();
    {
        dim3 g(KI / 32, BATCH / 32), b(32, 8);
        k_out<<<g, b>>>((float*)d_out);
    }
}

// round 8
// speedup vs baseline: 1.1171x; 1.1171x over previous
#include <cuda_runtime.h>

// ---------------- problem constants (fixed for this dataset) ----------------
#define Zl    384
#define MBr   46
#define DEGc  7
#define NBc   68
#define BEe   (MBr*DEGc)      // 322 base edges
#define NLD   (NBc*Zl)        // 26112 variable nodes
#define MCK   (MBr*Zl)        // 17664 check nodes
#define EDG   (BEe*Zl)        // 123648 edges
#define BATCH 128
#define B4    32              // batch in float4 units (array stride)
#define B4H   16              // per-chain float4 slots (batch 64)
#define KI    8448            // info bits out
#define NIN   25344           // received LLRs per batch row
#define NITER 20
#define LLRMAX 20.0f

// ---------------- static device scratch (no allocations allowed) ------------
// Single in-place edge message buffer: holds m_vc before k_cn, m_cv after.
// Footprint: 63.3 + 13.4 + 13.4 = ~90MB  -> resident in 126MB L2.
__device__ float4   g_msg[EDG*B4];      // edge messages (in-place)  63.3MB
__device__ float4   g_x[NLD*B4];        // final VN totals           13.4MB
__device__ float4   g_lch[NLD*B4];      // channel LLR (-clip)       13.4MB
__device__ unsigned g_bec[BEe];         // per base-edge: (c<<10)|shift
__device__ unsigned g_colptr[NBc+1];    // CSR over base columns
__device__ unsigned g_colent[BEe];      // (base_edge<<10)|shift

// ---------------- graph decode + CSR build (once per launch) ----------------
__global__ void k_build(const int* __restrict__ col) {
    int t = threadIdx.x;
    if (t < BEe) {
        int val = col[t * Zl];          // i=0 edge of this base-edge block
        g_bec[t] = ((unsigned)(val / Zl) << 10) | (unsigned)(val % Zl);
    }
    __syncthreads();
    if (t == 0) {
        unsigned cnt[NBc];
        for (int c = 0; c < NBc; c++) cnt[c] = 0;
        for (int e = 0; e < BEe; e++) cnt[g_bec[e] >> 10]++;
        unsigned run = 0;
        for (int c = 0; c < NBc; c++) { g_colptr[c] = run; run += cnt[c]; }
        g_colptr[NBc] = run;
        unsigned pos[NBc];
        for (int c = 0; c < NBc; c++) pos[c] = 0;
        for (int e = 0; e < BEe; e++) {
            unsigned c = g_bec[e] >> 10;
            g_colent[g_colptr[c] + pos[c]++] = ((unsigned)e << 10) | (g_bec[e] & 1023u);
        }
    }
}

// zero the punctured region of g_lch (first 2*Z variable nodes)
__global__ void k_zero() {
    int t = blockIdx.x * blockDim.x + threadIdx.x;   // 384*256 = 98304 = 768*128
    ((float*)g_lch)[t] = 0.0f;
}

// transpose + clip + negate channel LLRs: lch[(768+n)*128+b] = -clip(llr[b*NIN+n])
__global__ void k_lch(const float* __restrict__ llr) {
    __shared__ float tile[32][33];
    int n0 = blockIdx.x * 32, b0 = blockIdx.y * 32;
    int tx = threadIdx.x, ty = threadIdx.y;          // block (32, 8)
    float* lch = (float*)g_lch;
#pragma unroll
    for (int k = 0; k < 4; k++)
        tile[ty + k*8][tx] = llr[(size_t)(b0 + ty + k*8) * NIN + (n0 + tx)];
    __syncthreads();
#pragma unroll
    for (int k = 0; k < 4; k++) {
        float v = tile[tx][ty + k*8];
        v = fminf(fmaxf(v, -LLRMAX), LLRMAX);
        lch[(size_t)(768 + n0 + ty + k*8) * BATCH + (b0 + tx)] = -v;
    }
}

// ---------------- check-node update (min-sum, exclude-self) -----------------
// Branchless. Tie handling matches reference first-argmin exactly: on a tie
// m2 == m1, so (mag==m1 ? m2 : m1) gives the same value either way.
#define CNCOMP(F)                                                              \
    {                                                                          \
        float m1 = fabsf(v[0].F), m2 = 1e30f;                                  \
        unsigned par = __float_as_uint(v[0].F);                                \
        _Pragma("unroll")                                                      \
        for (int d = 1; d < DEGc; d++) {                                       \
            float mag = fabsf(v[d].F);                                         \
            m2 = fminf(m2, fmaxf(m1, mag));                                    \
            m1 = fminf(m1, mag);                                               \
            par ^= __float_as_uint(v[d].F);                                    \
        }                                                                      \
        par &= 0x80000000u;                                                    \
        _Pragma("unroll")                                                      \
        for (int d = 0; d < DEGc; d++) {                                       \
            unsigned bits = __float_as_uint(v[d].F);                           \
            float mag = fabsf(v[d].F);                                         \
            float sel = (mag == m1) ? m2 : m1;                                 \
            unsigned s = (par ^ bits) & 0x80000000u;                           \
            v[d].F = __uint_as_float(__float_as_uint(sel) | s);                \
        }                                                                      \
    }

template<bool FIRST>
__global__ void __launch_bounds__(256) k_cn(int ofs) {
    int tid = blockIdx.x * 256 + threadIdx.x;    // MCK*B4H = 282624 = 1104*256
    int b4 = (tid & (B4H - 1)) + ofs;            // batch slot within chain
    int m  = tid >> 4;                           // check index
    int r  = m / Zl;
    int i  = m - r * Zl;
    int beb  = r * DEGc;
    int base = (beb * Zl + i) * B4 + b4;

    float4 v[DEGc];
    if (FIRST) {
        // iteration 0: m_cv == 0 so m_vc == lch[col]; gather channel LLRs
#pragma unroll
        for (int d = 0; d < DEGc; d++) {
            unsigned u = g_bec[beb + d];
            int c  = (int)(u >> 10);
            int sh = (int)(u & 1023u);
            int iv = i + sh; if (iv >= Zl) iv -= Zl;
            v[d] = __ldg(&g_lch[(c * Zl + iv) * B4 + b4]);
        }
    } else {
        // steady state: m_vc stored contiguously (in place) by the VN kernel
#pragma unroll
        for (int d = 0; d < DEGc; d++)
            v[d] = g_msg[base + d * (Zl * B4)];
    }

    CNCOMP(x) CNCOMP(y) CNCOMP(z) CNCOMP(w)

    // in-place overwrite: buffer now holds m_cv
#pragma unroll
    for (int d = 0; d < DEGc; d++)
        g_msg[base + d * (Zl * B4)] = v[d];
}

// ---------------- variable-node update: m_vc = acc - m_cv, in place ---------
template<bool LAST>
__global__ void __launch_bounds__(256) k_vn(int ofs) {
    int tid = blockIdx.x * 256 + threadIdx.x;    // NLD*B4H = 417792 = 1632*256
    int b4 = (tid & (B4H - 1)) + ofs;
    int v  = tid >> 4;
    int c  = v / Zl;
    int i  = v - c * Zl;
    float4 acc = g_lch[v * B4 + b4];
    unsigned j0 = g_colptr[c], j1 = g_colptr[c + 1];
    // pass 1: accumulate total (coalesced 256B per edge per half-warp)
    for (unsigned j = j0; j < j1; j++) {
        unsigned u = g_colent[j];
        int be = (int)(u >> 10);
        int sh = (int)(u & 1023u);
        int ic = i - sh; if (ic < 0) ic += Zl;
        float4 t = __ldg(&g_msg[(be * Zl + ic) * B4 + b4]);
        acc.x += t.x; acc.y += t.y; acc.z += t.z; acc.w += t.w;
    }
    if (LAST) {
        g_x[v * B4 + b4] = acc;
    } else {
        // pass 2: reload (L1-hot) and overwrite with extrinsic VN->CN messages
        for (unsigned j = j0; j < j1; j++) {
            unsigned u = g_colent[j];
            int be = (int)(u >> 10);
            int sh = (int)(u & 1023u);
            int ic = i - sh; if (ic < 0) ic += Zl;
            int idx = (be * Zl + ic) * B4 + b4;
            float4 t = __ldg(&g_msg[idx]);
            g_msg[idx] = make_float4(acc.x - t.x, acc.y - t.y,
                                     acc.z - t.z, acc.w - t.w);
        }
    }
}

// ---------------- output: out[b*K+n] = -x[n*128+b], n<K ---------------------
__global__ void k_out(float* __restrict__ out) {
    __shared__ float tile[32][33];
    const float* xf = (const float*)g_x;
    int n0 = blockIdx.x * 32, b0 = blockIdx.y * 32;
    int tx = threadIdx.x, ty = threadIdx.y;      // block (32, 8)
#pragma unroll
    for (int k = 0; k < 4; k++)
        tile[ty + k*8][tx] = xf[(size_t)(n0 + ty + k*8) * BATCH + (b0 + tx)];
    __syncthreads();
#pragma unroll
    for (int k = 0; k < 4; k++)
        out[(size_t)(b0 + ty + k*8) * KI + (n0 + tx)] = -tile[tx][ty + k*8];
}

// ---------------- launch: two independent batch chains on forked streams ----
static void run_chain(cudaStream_t s, int ofs) {
    k_cn<true><<<(MCK * B4H) / 256, 256, 0, s>>>(ofs);
    k_vn<false><<<(NLD * B4H) / 256, 256, 0, s>>>(ofs);
    for (int it = 1; it < NITER - 1; it++) {
        k_cn<false><<<(MCK * B4H) / 256, 256, 0, s>>>(ofs);
        k_vn<false><<<(NLD * B4H) / 256, 256, 0, s>>>(ofs);
    }
    k_cn<false><<<(MCK * B4H) / 256, 256, 0, s>>>(ofs);
    k_vn<true><<<(NLD * B4H) / 256, 256, 0, s>>>(ofs);
}

extern "C" void kernel_launch(void* const* d_in, const int* in_sizes, int n_in,
                              void* d_out, int out_size) {
    const float* llr = (const float*)d_in[0];
    const int*   col = (const int*)d_in[2];

    // host-side infra objects, created once on the (non-captured) first call
    static cudaStream_t sB = 0;
    static cudaEvent_t  evFork = 0, evJoin = 0;
    static bool tried = false;
    if (!tried) {
        tried = true;
        if (cudaStreamCreateWithFlags(&sB, cudaStreamNonBlocking) != cudaSuccess) sB = 0;
        cudaEventCreateWithFlags(&evFork, cudaEventDisableTiming);
        cudaEventCreateWithFlags(&evJoin, cudaEventDisableTiming);
    }

    k_build<<<1, 512>>>(col);
    k_zero<<<384, 256>>>();
    {
        dim3 g(NIN / 32, BATCH / 32), b(32, 8);
        k_lch<<<g, b>>>(llr);
    }

    if (sB) {
        cudaEventRecord(evFork, 0);
        cudaStreamWaitEvent(sB, evFork, 0);
        run_chain(0,  0);        // chain A: batch slots [0,16)  on main stream
        run_chain(sB, B4H);      // chain B: batch slots [16,32) on forked stream
        cudaEventRecord(evJoin, sB);
        cudaStreamWaitEvent(0, evJoin, 0);
    } else {
        run_chain(0, 0);
        run_chain(0, B4H);
    }

    {
        dim3 g(KI / 32, BATCH / 32), b(32, 8);
        k_out<<<g, b>>>((float*)d_out);
    }
}

// round 9
// speedup vs baseline: 1.1176x; 1.0005x over previous
#include <cuda_runtime.h>

// ---------------- problem constants (fixed for this dataset) ----------------
#define Zl    384
#define MBr   46
#define DEGc  7
#define NBc   68
#define BEe   (MBr*DEGc)      // 322 base edges
#define NLD   (NBc*Zl)        // 26112 variable nodes
#define MCK   (MBr*Zl)        // 17664 check nodes
#define EDG   (BEe*Zl)        // 123648 edges
#define BATCH 128
#define B4    32              // batch in float4 units (array stride)
#define B4Q   8               // per-chain float4 slots (batch 32)
#define NCH   4               // chains
#define KI    8448            // info bits out
#define NIN   25344           // received LLRs per batch row
#define NITER 20
#define LLRMAX 20.0f

// ---------------- static device scratch (no allocations allowed) ------------
// Single in-place edge message buffer: holds m_vc before k_cn, m_cv after.
// Footprint: 63.3 + 13.4 + 13.4 = ~90MB  -> resident in 126MB L2.
__device__ float4   g_msg[EDG*B4];      // edge messages (in-place)  63.3MB
__device__ float4   g_x[NLD*B4];        // final VN totals           13.4MB
__device__ float4   g_lch[NLD*B4];      // channel LLR (-clip)       13.4MB
__device__ unsigned g_bec[BEe];         // per base-edge: (c<<10)|shift
__device__ unsigned g_colptr[NBc+1];    // CSR over base columns
__device__ unsigned g_colent[BEe];      // (base_edge<<10)|shift

// ---------------- graph decode + CSR build (once per launch) ----------------
__global__ void k_build(const int* __restrict__ col) {
    int t = threadIdx.x;
    if (t < BEe) {
        int val = col[t * Zl];          // i=0 edge of this base-edge block
        g_bec[t] = ((unsigned)(val / Zl) << 10) | (unsigned)(val % Zl);
    }
    __syncthreads();
    if (t == 0) {
        unsigned cnt[NBc];
        for (int c = 0; c < NBc; c++) cnt[c] = 0;
        for (int e = 0; e < BEe; e++) cnt[g_bec[e] >> 10]++;
        unsigned run = 0;
        for (int c = 0; c < NBc; c++) { g_colptr[c] = run; run += cnt[c]; }
        g_colptr[NBc] = run;
        unsigned pos[NBc];
        for (int c = 0; c < NBc; c++) pos[c] = 0;
        for (int e = 0; e < BEe; e++) {
            unsigned c = g_bec[e] >> 10;
            g_colent[g_colptr[c] + pos[c]++] = ((unsigned)e << 10) | (g_bec[e] & 1023u);
        }
    }
}

// zero the punctured region of g_lch (first 2*Z variable nodes)
__global__ void k_zero() {
    int t = blockIdx.x * blockDim.x + threadIdx.x;   // 384*256 = 98304 = 768*128
    ((float*)g_lch)[t] = 0.0f;
}

// transpose + clip + negate channel LLRs: lch[(768+n)*128+b] = -clip(llr[b*NIN+n])
__global__ void k_lch(const float* __restrict__ llr) {
    __shared__ float tile[32][33];
    int n0 = blockIdx.x * 32, b0 = blockIdx.y * 32;
    int tx = threadIdx.x, ty = threadIdx.y;          // block (32, 8)
    float* lch = (float*)g_lch;
#pragma unroll
    for (int k = 0; k < 4; k++)
        tile[ty + k*8][tx] = llr[(size_t)(b0 + ty + k*8) * NIN + (n0 + tx)];
    __syncthreads();
#pragma unroll
    for (int k = 0; k < 4; k++) {
        float v = tile[tx][ty + k*8];
        v = fminf(fmaxf(v, -LLRMAX), LLRMAX);
        lch[(size_t)(768 + n0 + ty + k*8) * BATCH + (b0 + tx)] = -v;
    }
}

// ---------------- check-node update (min-sum, exclude-self) -----------------
// Branchless. Tie handling matches reference first-argmin exactly: on a tie
// m2 == m1, so (mag==m1 ? m2 : m1) gives the same value either way.
#define CNCOMP(F)                                                              \
    {                                                                          \
        float m1 = fabsf(v[0].F), m2 = 1e30f;                                  \
        unsigned par = __float_as_uint(v[0].F);                                \
        _Pragma("unroll")                                                      \
        for (int d = 1; d < DEGc; d++) {                                       \
            float mag = fabsf(v[d].F);                                         \
            m2 = fminf(m2, fmaxf(m1, mag));                                    \
            m1 = fminf(m1, mag);                                               \
            par ^= __float_as_uint(v[d].F);                                    \
        }                                                                      \
        par &= 0x80000000u;                                                    \
        _Pragma("unroll")                                                      \
        for (int d = 0; d < DEGc; d++) {                                       \
            unsigned bits = __float_as_uint(v[d].F);                           \
            float mag = fabsf(v[d].F);                                         \
            float sel = (mag == m1) ? m2 : m1;                                 \
            unsigned s = (par ^ bits) & 0x80000000u;                           \
            v[d].F = __uint_as_float(__float_as_uint(sel) | s);                \
        }                                                                      \
    }

template<bool FIRST>
__global__ void __launch_bounds__(256) k_cn(int ofs) {
    int tid = blockIdx.x * 256 + threadIdx.x;    // MCK*B4Q = 141312 = 552*256
    int b4 = (tid & (B4Q - 1)) + ofs;            // batch slot within chain
    int m  = tid >> 3;                           // check index
    int r  = m / Zl;
    int i  = m - r * Zl;
    int beb  = r * DEGc;
    int base = (beb * Zl + i) * B4 + b4;

    float4 v[DEGc];
    if (FIRST) {
        // iteration 0: m_cv == 0 so m_vc == lch[col]; gather channel LLRs
#pragma unroll
        for (int d = 0; d < DEGc; d++) {
            unsigned u = g_bec[beb + d];
            int c  = (int)(u >> 10);
            int sh = (int)(u & 1023u);
            int iv = i + sh; if (iv >= Zl) iv -= Zl;
            v[d] = __ldg(&g_lch[(c * Zl + iv) * B4 + b4]);
        }
    } else {
        // steady state: m_vc stored contiguously (in place) by the VN kernel
#pragma unroll
        for (int d = 0; d < DEGc; d++)
            v[d] = g_msg[base + d * (Zl * B4)];
    }

    CNCOMP(x) CNCOMP(y) CNCOMP(z) CNCOMP(w)

    // in-place overwrite: buffer now holds m_cv
#pragma unroll
    for (int d = 0; d < DEGc; d++)
        g_msg[base + d * (Zl * B4)] = v[d];
}

// ---------------- variable-node update: m_vc = acc - m_cv, in place ---------
template<bool LAST>
__global__ void __launch_bounds__(256) k_vn(int ofs) {
    int tid = blockIdx.x * 256 + threadIdx.x;    // NLD*B4Q = 208896 = 816*256
    int b4 = (tid & (B4Q - 1)) + ofs;
    int v  = tid >> 3;
    int c  = v / Zl;
    int i  = v - c * Zl;
    float4 acc = g_lch[v * B4 + b4];
    unsigned j0 = g_colptr[c], j1 = g_colptr[c + 1];
    // pass 1: accumulate total (each 8-lane group reads one 128B line per edge)
    for (unsigned j = j0; j < j1; j++) {
        unsigned u = g_colent[j];
        int be = (int)(u >> 10);
        int sh = (int)(u & 1023u);
        int ic = i - sh; if (ic < 0) ic += Zl;
        float4 t = __ldg(&g_msg[(be * Zl + ic) * B4 + b4]);
        acc.x += t.x; acc.y += t.y; acc.z += t.z; acc.w += t.w;
    }
    if (LAST) {
        g_x[v * B4 + b4] = acc;
    } else {
        // pass 2: reload (L1-hot) and overwrite with extrinsic VN->CN messages
        for (unsigned j = j0; j < j1; j++) {
            unsigned u = g_colent[j];
            int be = (int)(u >> 10);
            int sh = (int)(u & 1023u);
            int ic = i - sh; if (ic < 0) ic += Zl;
            int idx = (be * Zl + ic) * B4 + b4;
            float4 t = __ldg(&g_msg[idx]);
            g_msg[idx] = make_float4(acc.x - t.x, acc.y - t.y,
                                     acc.z - t.z, acc.w - t.w);
        }
    }
}

// ---------------- output: out[b*K+n] = -x[n*128+b], n<K ---------------------
__global__ void k_out(float* __restrict__ out) {
    __shared__ float tile[32][33];
    const float* xf = (const float*)g_x;
    int n0 = blockIdx.x * 32, b0 = blockIdx.y * 32;
    int tx = threadIdx.x, ty = threadIdx.y;      // block (32, 8)
#pragma unroll
    for (int k = 0; k < 4; k++)
        tile[ty + k*8][tx] = xf[(size_t)(n0 + ty + k*8) * BATCH + (b0 + tx)];
    __syncthreads();
#pragma unroll
    for (int k = 0; k < 4; k++)
        out[(size_t)(b0 + ty + k*8) * KI + (n0 + tx)] = -tile[tx][ty + k*8];
}

// ---------------- launch: four independent batch chains on forked streams ---
static void run_chain(cudaStream_t s, int ofs) {
    k_cn<true><<<(MCK * B4Q) / 256, 256, 0, s>>>(ofs);
    k_vn<false><<<(NLD * B4Q) / 256, 256, 0, s>>>(ofs);
    for (int it = 1; it < NITER - 1; it++) {
        k_cn<false><<<(MCK * B4Q) / 256, 256, 0, s>>>(ofs);
        k_vn<false><<<(NLD * B4Q) / 256, 256, 0, s>>>(ofs);
    }
    k_cn<false><<<(MCK * B4Q) / 256, 256, 0, s>>>(ofs);
    k_vn<true><<<(NLD * B4Q) / 256, 256, 0, s>>>(ofs);
}

extern "C" void kernel_launch(void* const* d_in, const int* in_sizes, int n_in,
                              void* d_out, int out_size) {
    const float* llr = (const float*)d_in[0];
    const int*   col = (const int*)d_in[2];

    // host-side infra objects, created once on the (non-captured) first call
    static cudaStream_t st[NCH - 1] = {0, 0, 0};
    static cudaEvent_t  evFork = 0;
    static cudaEvent_t  evJoin[NCH - 1] = {0, 0, 0};
    static bool tried = false, ok = false;
    if (!tried) {
        tried = true;
        ok = true;
        for (int k = 0; k < NCH - 1; k++)
            if (cudaStreamCreateWithFlags(&st[k], cudaStreamNonBlocking) != cudaSuccess) ok = false;
        if (cudaEventCreateWithFlags(&evFork, cudaEventDisableTiming) != cudaSuccess) ok = false;
        for (int k = 0; k < NCH - 1; k++)
            if (cudaEventCreateWithFlags(&evJoin[k], cudaEventDisableTiming) != cudaSuccess) ok = false;
    }

    k_build<<<1, 512>>>(col);
    k_zero<<<384, 256>>>();
    {
        dim3 g(NIN / 32, BATCH / 32), b(32, 8);
        k_lch<<<g, b>>>(llr);
    }

    if (ok) {
        cudaEventRecord(evFork, 0);
        for (int k = 0; k < NCH - 1; k++)
            cudaStreamWaitEvent(st[k], evFork, 0);
        run_chain(0, 0);                         // chain 0 on main stream
        for (int k = 0; k < NCH - 1; k++)
            run_chain(st[k], (k + 1) * B4Q);     // chains 1..3 on forked streams
        for (int k = 0; k < NCH - 1; k++) {
            cudaEventRecord(evJoin[k], st[k]);
            cudaStreamWaitEvent(0, evJoin[k], 0);
        }
    } else {
        for (int k = 0; k < NCH; k++)
            run_chain(0, k * B4Q);
    }

    {
        dim3 g(KI / 32, BATCH / 32), b(32, 8);
        k_out<<<g, b>>>((float*)d_out);
    }
}

// round 10
// speedup vs baseline: 1.1993x; 1.0731x over previous
#include <cuda_runtime.h>

// ---------------- problem constants (fixed for this dataset) ----------------
#define Zl    384
#define MBr   46
#define DEGc  7
#define NBc   68
#define BEe   (MBr*DEGc)      // 322 base edges
#define NLD   (NBc*Zl)        // 26112 variable nodes
#define MCK   (MBr*Zl)        // 17664 check nodes
#define EDG   (BEe*Zl)        // 123648 edges
#define BATCH 128
#define B4    32              // batch in float4 units (array stride)
#define B4Q   8               // per-chain float4 slots (batch 32)
#define NCH   4               // chains
#define KI    8448            // info bits out  (= 22*Zl)
#define KCOLS 22              // info base columns
#define NIN   25344           // received LLRs per batch row
#define NITER 20
#define LLRMAX 20.0f

// ---------------- static device scratch (no allocations allowed) ------------
// Single in-place edge message buffer: holds m_vc before k_cn, m_cv after.
// Footprint: 63.3 + 13.4 + 13.4 = ~90MB  -> resident in 126MB L2.
__device__ float4   g_msg[EDG*B4];      // edge messages (in-place)  63.3MB
__device__ float4   g_x[NLD*B4];        // final VN totals           13.4MB
__device__ float4   g_lch[NLD*B4];      // channel LLR (-clip)       13.4MB
__device__ unsigned g_bec[BEe];         // per base-edge: (c<<10)|shift
__device__ unsigned g_colptr[NBc+1];    // CSR over base columns
__device__ unsigned g_colent[BEe];      // (base_edge<<10)|shift

// ---------------- graph decode + CSR build (parallel, once per launch) ------
__global__ void k_build(const int* __restrict__ col) {
    __shared__ unsigned bec[BEe];
    int t = threadIdx.x;                 // 512 threads
    if (t < BEe) {
        int val = col[t * Zl];           // i=0 edge of this base-edge block
        unsigned u = ((unsigned)(val / Zl) << 10) | (unsigned)(val % Zl);
        bec[t] = u;
        g_bec[t] = u;
    }
    __syncthreads();
    if (t < NBc) {
        unsigned tc = (unsigned)t;
        unsigned off = 0, cnt = 0;
        for (int e = 0; e < BEe; e++) {
            unsigned c = bec[e] >> 10;
            off += (c < tc);
            cnt += (c == tc);
        }
        g_colptr[t] = off;
        if (t == NBc - 1) g_colptr[NBc] = off + cnt;
        unsigned pos = off;
        for (int e = 0; e < BEe; e++)
            if ((bec[e] >> 10) == tc)
                g_colent[pos++] = ((unsigned)e << 10) | (bec[e] & 1023u);
    }
}

// zero the punctured region of g_lch (first 2*Z variable nodes)
__global__ void k_zero() {
    int t = blockIdx.x * blockDim.x + threadIdx.x;   // 384*256 = 98304 = 768*128
    ((float*)g_lch)[t] = 0.0f;
}

// transpose + clip + negate channel LLRs: lch[(768+n)*128+b] = -clip(llr[b*NIN+n])
__global__ void k_lch(const float* __restrict__ llr) {
    __shared__ float tile[32][33];
    int n0 = blockIdx.x * 32, b0 = blockIdx.y * 32;
    int tx = threadIdx.x, ty = threadIdx.y;          // block (32, 8)
    float* lch = (float*)g_lch;
#pragma unroll
    for (int k = 0; k < 4; k++)
        tile[ty + k*8][tx] = llr[(size_t)(b0 + ty + k*8) * NIN + (n0 + tx)];
    __syncthreads();
#pragma unroll
    for (int k = 0; k < 4; k++) {
        float v = tile[tx][ty + k*8];
        v = fminf(fmaxf(v, -LLRMAX), LLRMAX);
        lch[(size_t)(768 + n0 + ty + k*8) * BATCH + (b0 + tx)] = -v;
    }
}

// ---------------- check-node update (min-sum, exclude-self) -----------------
// Branchless. Tie handling matches reference first-argmin exactly: on a tie
// m2 == m1, so (mag==m1 ? m2 : m1) gives the same value either way.
#define CNCOMP(F)                                                              \
    {                                                                          \
        float m1 = fabsf(v[0].F), m2 = 1e30f;                                  \
        unsigned par = __float_as_uint(v[0].F);                                \
        _Pragma("unroll")                                                      \
        for (int d = 1; d < DEGc; d++) {                                       \
            float mag = fabsf(v[d].F);                                         \
            m2 = fminf(m2, fmaxf(m1, mag));                                    \
            m1 = fminf(m1, mag);                                               \
            par ^= __float_as_uint(v[d].F);                                    \
        }                                                                      \
        par &= 0x80000000u;                                                    \
        _Pragma("unroll")                                                      \
        for (int d = 0; d < DEGc; d++) {                                       \
            unsigned bits = __float_as_uint(v[d].F);                           \
            float mag = fabsf(v[d].F);                                         \
            float sel = (mag == m1) ? m2 : m1;                                 \
            unsigned s = (par ^ bits) & 0x80000000u;                           \
            v[d].F = __uint_as_float(__float_as_uint(sel) | s);                \
        }                                                                      \
    }

template<bool FIRST, bool LASTCN>
__global__ void __launch_bounds__(256) k_cn(int ofs) {
    int tid = blockIdx.x * 256 + threadIdx.x;    // MCK*B4Q = 141312 = 552*256
    int b4 = (tid & (B4Q - 1)) + ofs;            // batch slot within chain
    int m  = tid >> 3;                           // check index
    int r  = m / Zl;
    int i  = m - r * Zl;
    int beb  = r * DEGc;
    int base = (beb * Zl + i) * B4 + b4;

    float4 v[DEGc];
    if (FIRST) {
        // iteration 0: m_cv == 0 so m_vc == lch[col]; gather channel LLRs
#pragma unroll
        for (int d = 0; d < DEGc; d++) {
            unsigned u = g_bec[beb + d];
            int c  = (int)(u >> 10);
            int sh = (int)(u & 1023u);
            int iv = i + sh; if (iv >= Zl) iv -= Zl;
            v[d] = __ldg(&g_lch[(c * Zl + iv) * B4 + b4]);
        }
    } else {
        // steady state: m_vc stored contiguously (in place) by the VN kernel
#pragma unroll
        for (int d = 0; d < DEGc; d++)
            v[d] = g_msg[base + d * (Zl * B4)];
    }

    CNCOMP(x) CNCOMP(y) CNCOMP(z) CNCOMP(w)

    // in-place overwrite: buffer now holds m_cv. On the last iteration only
    // edges feeding info base-columns (<22) are consumed downstream.
#pragma unroll
    for (int d = 0; d < DEGc; d++) {
        if (LASTCN && (g_bec[beb + d] >> 10) >= KCOLS) continue;
        g_msg[base + d * (Zl * B4)] = v[d];
    }
}

// ---------------- variable-node update: m_vc = acc - m_cv, in place ---------
template<bool LAST>
__global__ void __launch_bounds__(256) k_vn(int ofs) {
    int tid = blockIdx.x * 256 + threadIdx.x;
    int b4 = (tid & (B4Q - 1)) + ofs;
    int v  = tid >> 3;
    int c  = v / Zl;
    int i  = v - c * Zl;
    float4 acc = g_lch[v * B4 + b4];
    unsigned j0 = g_colptr[c], j1 = g_colptr[c + 1];
    // pass 1: accumulate total (each 8-lane group reads one 128B line per edge)
    for (unsigned j = j0; j < j1; j++) {
        unsigned u = g_colent[j];
        int be = (int)(u >> 10);
        int sh = (int)(u & 1023u);
        int ic = i - sh; if (ic < 0) ic += Zl;
        float4 t = __ldg(&g_msg[(be * Zl + ic) * B4 + b4]);
        acc.x += t.x; acc.y += t.y; acc.z += t.z; acc.w += t.w;
    }
    if (LAST) {
        g_x[v * B4 + b4] = acc;
    } else {
        // pass 2: reload (L1-hot) and overwrite with extrinsic VN->CN messages
        for (unsigned j = j0; j < j1; j++) {
            unsigned u = g_colent[j];
            int be = (int)(u >> 10);
            int sh = (int)(u & 1023u);
            int ic = i - sh; if (ic < 0) ic += Zl;
            int idx = (be * Zl + ic) * B4 + b4;
            float4 t = __ldg(&g_msg[idx]);
            g_msg[idx] = make_float4(acc.x - t.x, acc.y - t.y,
                                     acc.z - t.z, acc.w - t.w);
        }
    }
}

// ---------------- output: out[b*K+n] = -x[n*128+b], n<K ---------------------
__global__ void k_out(float* __restrict__ out) {
    __shared__ float tile[32][33];
    const float* xf = (const float*)g_x;
    int n0 = blockIdx.x * 32, b0 = blockIdx.y * 32;
    int tx = threadIdx.x, ty = threadIdx.y;      // block (32, 8)
#pragma unroll
    for (int k = 0; k < 4; k++)
        tile[ty + k*8][tx] = xf[(size_t)(n0 + ty + k*8) * BATCH + (b0 + tx)];
    __syncthreads();
#pragma unroll
    for (int k = 0; k < 4; k++)
        out[(size_t)(b0 + ty + k*8) * KI + (n0 + tx)] = -tile[tx][ty + k*8];
}

// ---------------- launch: four independent batch chains on forked streams ---
static void run_chain(cudaStream_t s, int ofs) {
    k_cn<true, false><<<(MCK * B4Q) / 256, 256, 0, s>>>(ofs);
    k_vn<false><<<(NLD * B4Q) / 256, 256, 0, s>>>(ofs);
    for (int it = 1; it < NITER - 1; it++) {
        k_cn<false, false><<<(MCK * B4Q) / 256, 256, 0, s>>>(ofs);
        k_vn<false><<<(NLD * B4Q) / 256, 256, 0, s>>>(ofs);
    }
    k_cn<false, true><<<(MCK * B4Q) / 256, 256, 0, s>>>(ofs);
    // final VN: only info vars (v < KI) are read by k_out
    k_vn<true><<<(KI * B4Q) / 256, 256, 0, s>>>(ofs);
}

extern "C" void kernel_launch(void* const* d_in, const int* in_sizes, int n_in,
                              void* d_out, int out_size) {
    const float* llr = (const float*)d_in[0];
    const int*   col = (const int*)d_in[2];

    // host-side infra objects, created once on the (non-captured) first call
    static cudaStream_t st[NCH - 1] = {0, 0, 0};
    static cudaEvent_t  evFork = 0, evSet = 0, evFork2 = 0;
    static cudaEvent_t  evJoin[NCH - 1] = {0, 0, 0};
    static bool tried = false, ok = false;
    if (!tried) {
        tried = true;
        ok = true;
        for (int k = 0; k < NCH - 1; k++)
            if (cudaStreamCreateWithFlags(&st[k], cudaStreamNonBlocking) != cudaSuccess) ok = false;
        if (cudaEventCreateWithFlags(&evFork, cudaEventDisableTiming) != cudaSuccess) ok = false;
        if (cudaEventCreateWithFlags(&evSet, cudaEventDisableTiming) != cudaSuccess) ok = false;
        if (cudaEventCreateWithFlags(&evFork2, cudaEventDisableTiming) != cudaSuccess) ok = false;
        for (int k = 0; k < NCH - 1; k++)
            if (cudaEventCreateWithFlags(&evJoin[k], cudaEventDisableTiming) != cudaSuccess) ok = false;
    }

    if (ok) {
        // setup: k_build (main) overlapped with k_zero + k_lch (st[0])
        cudaEventRecord(evFork, 0);
        cudaStreamWaitEvent(st[0], evFork, 0);
        k_zero<<<384, 256, 0, st[0]>>>();
        {
            dim3 g(NIN / 32, BATCH / 32), b(32, 8);
            k_lch<<<g, b, 0, st[0]>>>(llr);
        }
        k_build<<<1, 512>>>(col);
        cudaEventRecord(evSet, st[0]);
        cudaStreamWaitEvent(0, evSet, 0);

        // fork into 4 chains
        cudaEventRecord(evFork2, 0);
        for (int k = 0; k < NCH - 1; k++)
            cudaStreamWaitEvent(st[k], evFork2, 0);
        run_chain(0, 0);                         // chain 0 on main stream
        for (int k = 0; k < NCH - 1; k++)
            run_chain(st[k], (k + 1) * B4Q);     // chains 1..3 on forked streams
        for (int k = 0; k < NCH - 1; k++) {
            cudaEventRecord(evJoin[k], st[k]);
            cudaStreamWaitEvent(0, evJoin[k], 0);
        }
    } else {
        k_build<<<1, 512>>>(col);
        k_zero<<<384, 256>>>();
        dim3 g(NIN / 32, BATCH / 32), b(32, 8);
        k_lch<<<g, b>>>(llr);
        for (int k = 0; k < NCH; k++)
            run_chain(0, k * B4Q);
    }

    {
        dim3 g(KI / 32, BATCH / 32), b(32, 8);
        k_out<<<g, b>>>((float*)d_out);
    }
}

// round 12
// speedup vs baseline: 1.2054x; 1.0051x over previous
#include <cuda_runtime.h>

// ---------------- problem constants (fixed for this dataset) ----------------
#define Zl    384
#define MBr   46
#define DEGc  7
#define NBc   68
#define BEe   (MBr*DEGc)      // 322 base edges
#define NLD   (NBc*Zl)        // 26112 variable nodes
#define MCK   (MBr*Zl)        // 17664 check nodes
#define EDG   (BEe*Zl)        // 123648 edges
#define BATCH 128
#define B4    32              // batch in float4 units (array stride)
#define B4Q   8               // per-chain float4 slots (batch 32)
#define NCH   4               // chains
#define KI    8448            // info bits out  (= 22*Zl)
#define KCOLS 22              // info base columns
#define NIN   25344           // received LLRs per batch row
#define NITER 20
#define LLRMAX 20.0f

// ---------------- static device scratch (no allocations allowed) ------------
// Single in-place edge message buffer: holds m_vc before k_cn, m_cv after.
// Footprint: 63.3 + 13.4 = ~77MB  -> resident in 126MB L2.
__device__ float4   g_msg[EDG*B4];      // edge messages (in-place)  63.3MB
__device__ float4   g_lch[NLD*B4];      // channel LLR (-clip)       13.4MB
__device__ unsigned g_bec[BEe];         // per base-edge: (c<<10)|shift
__device__ unsigned g_colptr[NBc+1];    // CSR over base columns
__device__ unsigned g_colent[BEe];      // (base_edge<<10)|shift

// ---------------- graph decode + CSR build (parallel, once per launch) ------
__global__ void k_build(const int* __restrict__ col) {
    __shared__ unsigned bec[BEe];
    int t = threadIdx.x;                 // 512 threads
    if (t < BEe) {
        int val = col[t * Zl];           // i=0 edge of this base-edge block
        unsigned u = ((unsigned)(val / Zl) << 10) | (unsigned)(val % Zl);
        bec[t] = u;
        g_bec[t] = u;
    }
    __syncthreads();
    if (t < NBc) {
        unsigned tc = (unsigned)t;
        unsigned off = 0, cnt = 0;
        for (int e = 0; e < BEe; e++) {
            unsigned c = bec[e] >> 10;
            off += (c < tc);
            cnt += (c == tc);
        }
        g_colptr[t] = off;
        if (t == NBc - 1) g_colptr[NBc] = off + cnt;
        unsigned pos = off;
        for (int e = 0; e < BEe; e++)
            if ((bec[e] >> 10) == tc)
                g_colent[pos++] = ((unsigned)e << 10) | (bec[e] & 1023u);
    }
}

// zero the punctured region of g_lch (first 2*Z variable nodes)
__global__ void k_zero() {
    int t = blockIdx.x * blockDim.x + threadIdx.x;   // 384*256 = 98304 = 768*128
    ((float*)g_lch)[t] = 0.0f;
}

// transpose + clip + negate channel LLRs: lch[(768+n)*128+b] = -clip(llr[b*NIN+n])
__global__ void k_lch(const float* __restrict__ llr) {
    __shared__ float tile[32][33];
    int n0 = blockIdx.x * 32, b0 = blockIdx.y * 32;
    int tx = threadIdx.x, ty = threadIdx.y;          // block (32, 8)
    float* lch = (float*)g_lch;
#pragma unroll
    for (int k = 0; k < 4; k++)
        tile[ty + k*8][tx] = llr[(size_t)(b0 + ty + k*8) * NIN + (n0 + tx)];
    __syncthreads();
#pragma unroll
    for (int k = 0; k < 4; k++) {
        float v = tile[tx][ty + k*8];
        v = fminf(fmaxf(v, -LLRMAX), LLRMAX);
        lch[(size_t)(768 + n0 + ty + k*8) * BATCH + (b0 + tx)] = -v;
    }
}

// ---------------- check-node update (min-sum, exclude-self) -----------------
// Branchless. Tie handling matches reference first-argmin exactly: on a tie
// m2 == m1, so (mag==m1 ? m2 : m1) gives the same value either way.
#define CNCOMP(F)                                                              \
    {                                                                          \
        float m1 = fabsf(v[0].F), m2 = 1e30f;                                  \
        unsigned par = __float_as_uint(v[0].F);                                \
        _Pragma("unroll")                                                      \
        for (int d = 1; d < DEGc; d++) {                                       \
            float mag = fabsf(v[d].F);                                         \
            m2 = fminf(m2, fmaxf(m1, mag));                                    \
            m1 = fminf(m1, mag);                                               \
            par ^= __float_as_uint(v[d].F);                                    \
        }                                                                      \
        par &= 0x80000000u;                                                    \
        _Pragma("unroll")                                                      \
        for (int d = 0; d < DEGc; d++) {                                       \
            unsigned bits = __float_as_uint(v[d].F);                           \
            float mag = fabsf(v[d].F);                                         \
            float sel = (mag == m1) ? m2 : m1;                                 \
            unsigned s = (par ^ bits) & 0x80000000u;                           \
            v[d].F = __uint_as_float(__float_as_uint(sel) | s);                \
        }                                                                      \
    }

template<bool FIRST, bool LASTCN>
__global__ void __launch_bounds__(256) k_cn(int ofs) {
    int tid = blockIdx.x * 256 + threadIdx.x;    // MCK*B4Q = 141312 = 552*256
    int b4 = (tid & (B4Q - 1)) + ofs;            // batch slot within chain
    int m  = tid >> 3;                           // check index
    int r  = m / Zl;
    int i  = m - r * Zl;
    int beb  = r * DEGc;
    int base = (beb * Zl + i) * B4 + b4;

    float4 v[DEGc];
    if (FIRST) {
        // iteration 0: m_cv == 0 so m_vc == lch[col]; gather channel LLRs
#pragma unroll
        for (int d = 0; d < DEGc; d++) {
            unsigned u = g_bec[beb + d];
            int c  = (int)(u >> 10);
            int sh = (int)(u & 1023u);
            int iv = i + sh; if (iv >= Zl) iv -= Zl;
            v[d] = __ldg(&g_lch[(c * Zl + iv) * B4 + b4]);
        }
    } else {
        // steady state: m_vc stored contiguously (in place) by the VN kernel
#pragma unroll
        for (int d = 0; d < DEGc; d++)
            v[d] = g_msg[base + d * (Zl * B4)];
    }

    CNCOMP(x) CNCOMP(y) CNCOMP(z) CNCOMP(w)

    // in-place overwrite: buffer now holds m_cv. On the last iteration only
    // edges feeding info base-columns (<22) are consumed downstream.
#pragma unroll
    for (int d = 0; d < DEGc; d++) {
        if (LASTCN && (g_bec[beb + d] >> 10) >= KCOLS) continue;
        g_msg[base + d * (Zl * B4)] = v[d];
    }
}

// ---------------- variable-node update: m_vc = acc - m_cv, in place ---------
__global__ void __launch_bounds__(256) k_vn(int ofs) {
    int tid = blockIdx.x * 256 + threadIdx.x;    // NLD*B4Q = 208896 = 816*256
    int b4 = (tid & (B4Q - 1)) + ofs;
    int v  = tid >> 3;
    int c  = v / Zl;
    int i  = v - c * Zl;
    float4 acc = g_lch[v * B4 + b4];
    unsigned j0 = g_colptr[c], j1 = g_colptr[c + 1];
    // pass 1: accumulate total (each 8-lane group reads one 128B line per edge)
    for (unsigned j = j0; j < j1; j++) {
        unsigned u = g_colent[j];
        int be = (int)(u >> 10);
        int sh = (int)(u & 1023u);
        int ic = i - sh; if (ic < 0) ic += Zl;
        float4 t = __ldg(&g_msg[(be * Zl + ic) * B4 + b4]);
        acc.x += t.x; acc.y += t.y; acc.z += t.z; acc.w += t.w;
    }
    // pass 2: reload (L1-hot) and overwrite with extrinsic VN->CN messages
    for (unsigned j = j0; j < j1; j++) {
        unsigned u = g_colent[j];
        int be = (int)(u >> 10);
        int sh = (int)(u & 1023u);
        int ic = i - sh; if (ic < 0) ic += Zl;
        int idx = (be * Zl + ic) * B4 + b4;
        float4 t = __ldg(&g_msg[idx]);
        g_msg[idx] = make_float4(acc.x - t.x, acc.y - t.y,
                                 acc.z - t.z, acc.w - t.w);
    }
}

// ---------------- fused finale: final VN total + transpose + negate ---------
// Per chain: computes x = lch + sum(m_cv) for info vars only and writes
// out[b*KI+n] = -x directly (identical fp32 sum order to k_vn pass 1).
__global__ void k_fin(int ofs, float* __restrict__ out) {
    __shared__ float tile[32][33];
    int n0 = blockIdx.x * 32;                    // KI/32 = 264 blocks
    int tx = threadIdx.x, ty = threadIdx.y;      // block (32, 8)
    int v  = n0 + tx;                            // info var (< KI)
    int b4 = ofs + ty;                           // chain's float4 slot
    int c  = v / Zl;
    int i  = v - c * Zl;
    float4 acc = g_lch[v * B4 + b4];
    unsigned j0 = g_colptr[c], j1 = g_colptr[c + 1];
    for (unsigned j = j0; j < j1; j++) {
        unsigned u = g_colent[j];
        int be = (int)(u >> 10);
        int sh = (int)(u & 1023u);
        int ic = i - sh; if (ic < 0) ic += Zl;
        float4 t = __ldg(&g_msg[(be * Zl + ic) * B4 + b4]);
        acc.x += t.x; acc.y += t.y; acc.z += t.z; acc.w += t.w;
    }
    tile[4*ty + 0][tx] = acc.x;
    tile[4*ty + 1][tx] = acc.y;
    tile[4*ty + 2][tx] = acc.z;
    tile[4*ty + 3][tx] = acc.w;
    __syncthreads();
    int bbase = 4 * ofs;                         // chain's first batch element
#pragma unroll
    for (int k = 0; k < 4; k++) {
        int bl = ty + 8 * k;
        out[(size_t)(bbase + bl) * KI + n0 + tx] = -tile[bl][tx];
    }
}

// ---------------- launch: four independent batch chains on forked streams ---
static void run_chain(cudaStream_t s, int ofs, float* out) {
    k_cn<true, false><<<(MCK * B4Q) / 256, 256, 0, s>>>(ofs);
    k_vn<<<(NLD * B4Q) / 256, 256, 0, s>>>(ofs);
    for (int it = 1; it < NITER - 1; it++) {
        k_cn<false, false><<<(MCK * B4Q) / 256, 256, 0, s>>>(ofs);
        k_vn<<<(NLD * B4Q) / 256, 256, 0, s>>>(ofs);
    }
    k_cn<false, true><<<(MCK * B4Q) / 256, 256, 0, s>>>(ofs);
    // fused finale: final totals for info vars -> transpose -> d_out
    {
        dim3 g(KI / 32), b(32, 8);
        k_fin<<<g, b, 0, s>>>(ofs, out);
    }
}

extern "C" void kernel_launch(void* const* d_in, const int* in_sizes, int n_in,
                              void* d_out, int out_size) {
    const float* llr = (const float*)d_in[0];
    const int*   col = (const int*)d_in[2];
    float*       out = (float*)d_out;

    // host-side infra objects, created once on the (non-captured) first call
    static cudaStream_t st[NCH - 1] = {0, 0, 0};
    static cudaEvent_t  evFork = 0, evSet = 0, evFork2 = 0;
    static cudaEvent_t  evJoin[NCH - 1] = {0, 0, 0};
    static bool tried = false, ok = false;
    if (!tried) {
        tried = true;
        ok = true;
        for (int k = 0; k < NCH - 1; k++)
            if (cudaStreamCreateWithFlags(&st[k], cudaStreamNonBlocking) != cudaSuccess) ok = false;
        if (cudaEventCreateWithFlags(&evFork, cudaEventDisableTiming) != cudaSuccess) ok = false;
        if (cudaEventCreateWithFlags(&evSet, cudaEventDisableTiming) != cudaSuccess) ok = false;
        if (cudaEventCreateWithFlags(&evFork2, cudaEventDisableTiming) != cudaSuccess) ok = false;
        for (int k = 0; k < NCH - 1; k++)
            if (cudaEventCreateWithFlags(&evJoin[k], cudaEventDisableTiming) != cudaSuccess) ok = false;
    }

    if (ok) {
        // setup: k_build (main) overlapped with k_zero + k_lch (st[0])
        cudaEventRecord(evFork, 0);
        cudaStreamWaitEvent(st[0], evFork, 0);
        k_zero<<<384, 256, 0, st[0]>>>();
        {
            dim3 g(NIN / 32, BATCH / 32), b(32, 8);
            k_lch<<<g, b, 0, st[0]>>>(llr);
        }
        k_build<<<1, 512>>>(col);
        cudaEventRecord(evSet, st[0]);
        cudaStreamWaitEvent(0, evSet, 0);

        // fork into 4 chains
        cudaEventRecord(evFork2, 0);
        for (int k = 0; k < NCH - 1; k++)
            cudaStreamWaitEvent(st[k], evFork2, 0);
        run_chain(0, 0, out);                    // chain 0 on main stream
        for (int k = 0; k < NCH - 1; k++)
            run_chain(st[k], (k + 1) * B4Q, out);
        for (int k = 0; k < NCH - 1; k++) {
            cudaEventRecord(evJoin[k], st[k]);
            cudaStreamWaitEvent(0, evJoin[k], 0);
        }
    } else {
        k_build<<<1, 512>>>(col);
        k_zero<<<384, 256>>>();
        dim3 g(NIN / 32, BATCH / 32), b(32, 8);
        k_lch<<<g, b>>>(llr);
        for (int k = 0; k < NCH; k++)
            run_chain(0, k * B4Q, out);
    }
}

// round 13
// speedup vs baseline: 1.2073x; 1.0016x over previous
#include <cuda_runtime.h>

// ---------------- problem constants (fixed for this dataset) ----------------
#define Zl    384
#define MBr   46
#define DEGc  7
#define NBc   68
#define BEe   (MBr*DEGc)      // 322 base edges
#define NLD   (NBc*Zl)        // 26112 variable nodes
#define MCK   (MBr*Zl)        // 17664 check nodes
#define EDG   (BEe*Zl)        // 123648 edges
#define BATCH 128
#define B4    32              // batch in float4 units (array stride)
#define B4Q   8               // per-chain float4 slots (batch 32)
#define NCH   4               // chains
#define KI    8448            // info bits out  (= 22*Zl)
#define KCOLS 22              // info base columns
#define NIN   25344           // received LLRs per batch row
#define NITER 20
#define LLRMAX 20.0f

// ---------------- static device scratch (no allocations allowed) ------------
// Single in-place edge message buffer: holds m_vc before k_cn, m_cv after.
// Footprint: 63.3 + 13.4 = ~77MB  -> resident in 126MB L2.
__device__ float4   g_msg[EDG*B4];      // edge messages (in-place)  63.3MB
__device__ float4   g_lch[NLD*B4];      // channel LLR (-clip)       13.4MB
__device__ unsigned g_bec[BEe];         // per base-edge: (c<<10)|shift
__device__ unsigned g_colptr[NBc+1];    // CSR over base columns
__device__ unsigned g_colent[BEe];      // (base_edge<<10)|shift

// ---------------- graph decode + CSR build (parallel, once per launch) ------
__global__ void k_build(const int* __restrict__ col) {
    __shared__ unsigned bec[BEe];
    int t = threadIdx.x;                 // 512 threads
    if (t < BEe) {
        int val = col[t * Zl];           // i=0 edge of this base-edge block
        unsigned u = ((unsigned)(val / Zl) << 10) | (unsigned)(val % Zl);
        bec[t] = u;
        g_bec[t] = u;
    }
    __syncthreads();
    if (t < NBc) {
        unsigned tc = (unsigned)t;
        unsigned off = 0, cnt = 0;
        for (int e = 0; e < BEe; e++) {
            unsigned c = bec[e] >> 10;
            off += (c < tc);
            cnt += (c == tc);
        }
        g_colptr[t] = off;
        if (t == NBc - 1) g_colptr[NBc] = off + cnt;
        unsigned pos = off;
        for (int e = 0; e < BEe; e++)
            if ((bec[e] >> 10) == tc)
                g_colent[pos++] = ((unsigned)e << 10) | (bec[e] & 1023u);
    }
}

// transpose + clip + negate channel LLRs: lch[(768+n)*128+b] = -clip(llr[b*NIN+n])
// plus zero-fill of the punctured region (first 2*Z vars) via 24 extra x-blocks.
__global__ void k_lch(const float* __restrict__ llr) {
    __shared__ float tile[32][33];
    float* lch = (float*)g_lch;
    int bx = blockIdx.x;
    int tx = threadIdx.x, ty = threadIdx.y;          // block (32, 8)
    if (bx >= NIN / 32) {
        // zero region: vars [0, 768) -> 768*128 floats = 24 blocks of 4096
        int zb = bx - NIN / 32;
        int t  = (zb * 256 + ty * 32 + tx) * 16;
#pragma unroll
        for (int k = 0; k < 4; k++)
            *reinterpret_cast<float4*>(&lch[t + 4 * k]) =
                make_float4(0.f, 0.f, 0.f, 0.f);
        return;
    }
    int n0 = bx * 32, b0 = blockIdx.y * 32;
#pragma unroll
    for (int k = 0; k < 4; k++)
        tile[ty + k*8][tx] = llr[(size_t)(b0 + ty + k*8) * NIN + (n0 + tx)];
    __syncthreads();
#pragma unroll
    for (int k = 0; k < 4; k++) {
        float v = tile[tx][ty + k*8];
        v = fminf(fmaxf(v, -LLRMAX), LLRMAX);
        lch[(size_t)(768 + n0 + ty + k*8) * BATCH + (b0 + tx)] = -v;
    }
}

// ---------------- check-node update (min-sum, exclude-self) -----------------
// Branchless. Tie handling matches reference first-argmin exactly: on a tie
// m2 == m1, so (mag==m1 ? m2 : m1) gives the same value either way.
#define CNCOMP(F)                                                              \
    {                                                                          \
        float m1 = fabsf(v[0].F), m2 = 1e30f;                                  \
        unsigned par = __float_as_uint(v[0].F);                                \
        _Pragma("unroll")                                                      \
        for (int d = 1; d < DEGc; d++) {                                       \
            float mag = fabsf(v[d].F);                                         \
            m2 = fminf(m2, fmaxf(m1, mag));                                    \
            m1 = fminf(m1, mag);                                               \
            par ^= __float_as_uint(v[d].F);                                    \
        }                                                                      \
        par &= 0x80000000u;                                                    \
        _Pragma("unroll")                                                      \
        for (int d = 0; d < DEGc; d++) {                                       \
            unsigned bits = __float_as_uint(v[d].F);                           \
            float mag = fabsf(v[d].F);                                         \
            float sel = (mag == m1) ? m2 : m1;                                 \
            unsigned s = (par ^ bits) & 0x80000000u;                           \
            v[d].F = __uint_as_float(__float_as_uint(sel) | s);                \
        }                                                                      \
    }

template<bool FIRST, bool LASTCN>
__global__ void __launch_bounds__(256) k_cn(int ofs) {
    int tid = blockIdx.x * 256 + threadIdx.x;    // MCK*B4Q = 141312 = 552*256
    int b4 = (tid & (B4Q - 1)) + ofs;            // batch slot within chain
    int m  = tid >> 3;                           // check index
    int r  = m / Zl;
    int i  = m - r * Zl;
    int beb  = r * DEGc;
    int base = (beb * Zl + i) * B4 + b4;

    float4 v[DEGc];
    if (FIRST) {
        // iteration 0: m_cv == 0 so m_vc == lch[col]; gather channel LLRs
#pragma unroll
        for (int d = 0; d < DEGc; d++) {
            unsigned u = g_bec[beb + d];
            int c  = (int)(u >> 10);
            int sh = (int)(u & 1023u);
            int iv = i + sh; if (iv >= Zl) iv -= Zl;
            v[d] = __ldg(&g_lch[(c * Zl + iv) * B4 + b4]);
        }
    } else {
        // steady state: m_vc stored contiguously (in place) by the VN kernel
#pragma unroll
        for (int d = 0; d < DEGc; d++)
            v[d] = g_msg[base + d * (Zl * B4)];
    }

    CNCOMP(x) CNCOMP(y) CNCOMP(z) CNCOMP(w)

    // in-place overwrite: buffer now holds m_cv. On the last iteration only
    // edges feeding info base-columns (<22) are consumed downstream.
#pragma unroll
    for (int d = 0; d < DEGc; d++) {
        if (LASTCN && (g_bec[beb + d] >> 10) >= KCOLS) continue;
        g_msg[base + d * (Zl * B4)] = v[d];
    }
}

// ---------------- variable-node update: m_vc = acc - m_cv, in place ---------
__global__ void __launch_bounds__(256) k_vn(int ofs) {
    int tid = blockIdx.x * 256 + threadIdx.x;    // NLD*B4Q = 208896 = 816*256
    int b4 = (tid & (B4Q - 1)) + ofs;
    int v  = tid >> 3;
    int c  = v / Zl;
    int i  = v - c * Zl;
    float4 acc = g_lch[v * B4 + b4];
    unsigned j0 = g_colptr[c], j1 = g_colptr[c + 1];
    // pass 1: accumulate total (each 8-lane group reads one 128B line per edge)
    for (unsigned j = j0; j < j1; j++) {
        unsigned u = g_colent[j];
        int be = (int)(u >> 10);
        int sh = (int)(u & 1023u);
        int ic = i - sh; if (ic < 0) ic += Zl;
        float4 t = __ldg(&g_msg[(be * Zl + ic) * B4 + b4]);
        acc.x += t.x; acc.y += t.y; acc.z += t.z; acc.w += t.w;
    }
    // pass 2: reload (L1-hot) and overwrite with extrinsic VN->CN messages
    for (unsigned j = j0; j < j1; j++) {
        unsigned u = g_colent[j];
        int be = (int)(u >> 10);
        int sh = (int)(u & 1023u);
        int ic = i - sh; if (ic < 0) ic += Zl;
        int idx = (be * Zl + ic) * B4 + b4;
        float4 t = __ldg(&g_msg[idx]);
        g_msg[idx] = make_float4(acc.x - t.x, acc.y - t.y,
                                 acc.z - t.z, acc.w - t.w);
    }
}

// ---------------- fused finale: final VN total + transpose + negate ---------
// Per chain: computes x = lch + sum(m_cv) for info vars only and writes
// out[b*KI+n] = -x directly (identical fp32 sum order to k_vn pass 1).
__global__ void k_fin(int ofs, float* __restrict__ out) {
    __shared__ float tile[32][33];
    int n0 = blockIdx.x * 32;                    // KI/32 = 264 blocks
    int tx = threadIdx.x, ty = threadIdx.y;      // block (32, 8)
    int v  = n0 + tx;                            // info var (< KI)
    int b4 = ofs + ty;                           // chain's float4 slot
    int c  = v / Zl;
    int i  = v - c * Zl;
    float4 acc = g_lch[v * B4 + b4];
    unsigned j0 = g_colptr[c], j1 = g_colptr[c + 1];
    for (unsigned j = j0; j < j1; j++) {
        unsigned u = g_colent[j];
        int be = (int)(u >> 10);
        int sh = (int)(u & 1023u);
        int ic = i - sh; if (ic < 0) ic += Zl;
        float4 t = __ldg(&g_msg[(be * Zl + ic) * B4 + b4]);
        acc.x += t.x; acc.y += t.y; acc.z += t.z; acc.w += t.w;
    }
    tile[4*ty + 0][tx] = acc.x;
    tile[4*ty + 1][tx] = acc.y;
    tile[4*ty + 2][tx] = acc.z;
    tile[4*ty + 3][tx] = acc.w;
    __syncthreads();
    int bbase = 4 * ofs;                         // chain's first batch element
#pragma unroll
    for (int k = 0; k < 4; k++) {
        int bl = ty + 8 * k;
        out[(size_t)(bbase + bl) * KI + n0 + tx] = -tile[bl][tx];
    }
}

// ---------------- launch: four independent batch chains on forked streams ---
static void run_chain(cudaStream_t s, int ofs, float* out) {
    k_cn<true, false><<<(MCK * B4Q) / 256, 256, 0, s>>>(ofs);
    k_vn<<<(NLD * B4Q) / 256, 256, 0, s>>>(ofs);
    for (int it = 1; it < NITER - 1; it++) {
        k_cn<false, false><<<(MCK * B4Q) / 256, 256, 0, s>>>(ofs);
        k_vn<<<(NLD * B4Q) / 256, 256, 0, s>>>(ofs);
    }
    k_cn<false, true><<<(MCK * B4Q) / 256, 256, 0, s>>>(ofs);
    // fused finale: final totals for info vars -> transpose -> d_out
    {
        dim3 g(KI / 32), b(32, 8);
        k_fin<<<g, b, 0, s>>>(ofs, out);
    }
}

extern "C" void kernel_launch(void* const* d_in, const int* in_sizes, int n_in,
                              void* d_out, int out_size) {
    const float* llr = (const float*)d_in[0];
    const int*   col = (const int*)d_in[2];
    float*       out = (float*)d_out;

    // host-side infra objects, created once on the (non-captured) first call
    static cudaStream_t st[NCH - 1] = {0, 0, 0};
    static cudaEvent_t  evFork = 0, evLch = 0, evBld = 0;
    static cudaEvent_t  evJoin[NCH - 1] = {0, 0, 0};
    static bool tried = false, ok = false;
    if (!tried) {
        tried = true;
        ok = true;
        for (int k = 0; k < NCH - 1; k++)
            if (cudaStreamCreateWithFlags(&st[k], cudaStreamNonBlocking) != cudaSuccess) ok = false;
        if (cudaEventCreateWithFlags(&evFork, cudaEventDisableTiming) != cudaSuccess) ok = false;
        if (cudaEventCreateWithFlags(&evLch, cudaEventDisableTiming) != cudaSuccess) ok = false;
        if (cudaEventCreateWithFlags(&evBld, cudaEventDisableTiming) != cudaSuccess) ok = false;
        for (int k = 0; k < NCH - 1; k++)
            if (cudaEventCreateWithFlags(&evJoin[k], cudaEventDisableTiming) != cudaSuccess) ok = false;
    }

    if (ok) {
        // setup: k_build (main) overlapped with merged k_lch (st[0])
        cudaEventRecord(evFork, 0);
        cudaStreamWaitEvent(st[0], evFork, 0);
        {
            dim3 g(NIN / 32 + 24, BATCH / 32), b(32, 8);   // +24 zero blocks
            k_lch<<<g, b, 0, st[0]>>>(llr);
        }
        k_build<<<1, 512>>>(col);
        cudaEventRecord(evLch, st[0]);
        cudaEventRecord(evBld, 0);

        // fork: every chain needs {build done, lch done}
        cudaStreamWaitEvent(0, evLch, 0);                  // main: has build, add lch
        cudaStreamWaitEvent(st[0], evBld, 0);              // st[0]: has lch, add build
        for (int k = 1; k < NCH - 1; k++) {
            cudaStreamWaitEvent(st[k], evLch, 0);
            cudaStreamWaitEvent(st[k], evBld, 0);
        }
        run_chain(0, 0, out);                              // chain 0 on main stream
        for (int k = 0; k < NCH - 1; k++)
            run_chain(st[k], (k + 1) * B4Q, out);          // chains 1..3
        for (int k = 0; k < NCH - 1; k++) {
            cudaEventRecord(evJoin[k], st[k]);
            cudaStreamWaitEvent(0, evJoin[k], 0);
        }
    } else {
        k_build<<<1, 512>>>(col);
        dim3 g(NIN / 32 + 24, BATCH / 32), b(32, 8);
        k_lch<<<g, b>>>(llr);
        for (int k = 0; k < NCH; k++)
            run_chain(0, k * B4Q, out);
    }
}

// round 14
// speedup vs baseline: 1.2103x; 1.0025x over previous
#include <cuda_runtime.h>

// ---------------- problem constants (fixed for this dataset) ----------------
#define Zl    384
#define MBr   46
#define DEGc  7
#define NBc   68
#define BEe   (MBr*DEGc)      // 322 base edges
#define NLD   (NBc*Zl)        // 26112 variable nodes
#define MCK   (MBr*Zl)        // 17664 check nodes
#define EDG   (BEe*Zl)        // 123648 edges
#define BATCH 128
#define B4    32              // batch in float4 units (array stride)
#define B4Q   8               // per-chain float4 slots (batch 32)
#define NCH   4               // chains
#define KI    8448            // info bits out  (= 22*Zl)
#define KCOLS 22              // info base columns
#define NIN   25344           // received LLRs per batch row
#define NITER 20
#define LLRMAX 20.0f

// ---------------- static device scratch (no allocations allowed) ------------
// Single in-place edge message buffer: holds m_vc before k_cn, m_cv after.
// Footprint: 63.3 + 13.4 = ~77MB  -> resident in 126MB L2.
__device__ float4   g_msg[EDG*B4];      // edge messages (in-place)  63.3MB
__device__ float4   g_lch[NLD*B4];      // channel LLR (-clip)       13.4MB
__device__ unsigned g_bec[BEe];         // per base-edge: (c<<10)|shift
__device__ unsigned g_colptr[NBc+1];    // CSR over base columns
__device__ unsigned g_colent[BEe];      // (base_edge<<10)|shift

// ---------------- graph decode + CSR build (parallel, once per launch) ------
__global__ void k_build(const int* __restrict__ col) {
    __shared__ unsigned bec[BEe];
    int t = threadIdx.x;                 // 512 threads
    if (t < BEe) {
        int val = col[t * Zl];           // i=0 edge of this base-edge block
        unsigned u = ((unsigned)(val / Zl) << 10) | (unsigned)(val % Zl);
        bec[t] = u;
        g_bec[t] = u;
    }
    __syncthreads();
    if (t < NBc) {
        unsigned tc = (unsigned)t;
        unsigned off = 0, cnt = 0;
        for (int e = 0; e < BEe; e++) {
            unsigned c = bec[e] >> 10;
            off += (c < tc);
            cnt += (c == tc);
        }
        g_colptr[t] = off;
        if (t == NBc - 1) g_colptr[NBc] = off + cnt;
        unsigned pos = off;
        for (int e = 0; e < BEe; e++)
            if ((bec[e] >> 10) == tc)
                g_colent[pos++] = ((unsigned)e << 10) | (bec[e] & 1023u);
    }
}

// Per-chain channel-LLR slice: transpose + clip + negate 32 batch rows into
// lch[(768+n)*128 + (bbase+tx)], plus zero-fill of the punctured region
// (vars [0,768)) for this chain's 8 float4 slots. ofs = chain's float4 base.
__global__ void k_lch(const float* __restrict__ llr, int ofs) {
    __shared__ float tile[32][33];
    float* lch = (float*)g_lch;
    int bx = blockIdx.x;
    int tx = threadIdx.x, ty = threadIdx.y;          // block (32, 8)
    int bbase = 4 * ofs;                             // first batch element
    if (bx >= NIN / 32) {
        // zero region: 768 vars x 8 float4 slots = 6144 float4 = 6 blocks x 1024
        int t = (bx - NIN / 32) * 1024 + ty * 128 + tx * 4;
#pragma unroll
        for (int j = 0; j < 4; j++) {
            int idx = t + j;                         // [0, 6144)
            int v   = idx >> 3;
            int sl  = idx & 7;
            g_msg[0]; // no-op; keep compiler happy about unused warnings
            g_lch[v * B4 + ofs + sl] = make_float4(0.f, 0.f, 0.f, 0.f);
        }
        return;
    }
    int n0 = bx * 32;
#pragma unroll
    for (int k = 0; k < 4; k++)
        tile[ty + k*8][tx] = llr[(size_t)(bbase + ty + k*8) * NIN + (n0 + tx)];
    __syncthreads();
#pragma unroll
    for (int k = 0; k < 4; k++) {
        float v = tile[tx][ty + k*8];
        v = fminf(fmaxf(v, -LLRMAX), LLRMAX);
        lch[(size_t)(768 + n0 + ty + k*8) * BATCH + (bbase + tx)] = -v;
    }
}

// ---------------- check-node update (min-sum, exclude-self) -----------------
// Branchless. Tie handling matches reference first-argmin exactly: on a tie
// m2 == m1, so (mag==m1 ? m2 : m1) gives the same value either way.
#define CNCOMP(F)                                                              \
    {                                                                          \
        float m1 = fabsf(v[0].F), m2 = 1e30f;                                  \
        unsigned par = __float_as_uint(v[0].F);                                \
        _Pragma("unroll")                                                      \
        for (int d = 1; d < DEGc; d++) {                                       \
            float mag = fabsf(v[d].F);                                         \
            m2 = fminf(m2, fmaxf(m1, mag));                                    \
            m1 = fminf(m1, mag);                                               \
            par ^= __float_as_uint(v[d].F);                                    \
        }                                                                      \
        par &= 0x80000000u;                                                    \
        _Pragma("unroll")                                                      \
        for (int d = 0; d < DEGc; d++) {                                       \
            unsigned bits = __float_as_uint(v[d].F);                           \
            float mag = fabsf(v[d].F);                                         \
            float sel = (mag == m1) ? m2 : m1;                                 \
            unsigned s = (par ^ bits) & 0x80000000u;                           \
            v[d].F = __uint_as_float(__float_as_uint(sel) | s);                \
        }                                                                      \
    }

template<bool FIRST, bool LASTCN>
__global__ void __launch_bounds__(256) k_cn(int ofs) {
    int tid = blockIdx.x * 256 + threadIdx.x;    // MCK*B4Q = 141312 = 552*256
    int b4 = (tid & (B4Q - 1)) + ofs;            // batch slot within chain
    int m  = tid >> 3;                           // check index
    int r  = m / Zl;
    int i  = m - r * Zl;
    int beb  = r * DEGc;
    int base = (beb * Zl + i) * B4 + b4;

    float4 v[DEGc];
    if (FIRST) {
        // iteration 0: m_cv == 0 so m_vc == lch[col]; gather channel LLRs
#pragma unroll
        for (int d = 0; d < DEGc; d++) {
            unsigned u = g_bec[beb + d];
            int c  = (int)(u >> 10);
            int sh = (int)(u & 1023u);
            int iv = i + sh; if (iv >= Zl) iv -= Zl;
            v[d] = __ldg(&g_lch[(c * Zl + iv) * B4 + b4]);
        }
    } else {
        // steady state: m_vc stored contiguously (in place) by the VN kernel
#pragma unroll
        for (int d = 0; d < DEGc; d++)
            v[d] = g_msg[base + d * (Zl * B4)];
    }

    CNCOMP(x) CNCOMP(y) CNCOMP(z) CNCOMP(w)

    // in-place overwrite: buffer now holds m_cv. On the last iteration only
    // edges feeding info base-columns (<22) are consumed downstream.
#pragma unroll
    for (int d = 0; d < DEGc; d++) {
        if (LASTCN && (g_bec[beb + d] >> 10) >= KCOLS) continue;
        g_msg[base + d * (Zl * B4)] = v[d];
    }
}

// ---------------- variable-node update: m_vc = acc - m_cv, in place ---------
__global__ void __launch_bounds__(256) k_vn(int ofs) {
    int tid = blockIdx.x * 256 + threadIdx.x;    // NLD*B4Q = 208896 = 816*256
    int b4 = (tid & (B4Q - 1)) + ofs;
    int v  = tid >> 3;
    int c  = v / Zl;
    int i  = v - c * Zl;
    float4 acc = g_lch[v * B4 + b4];
    unsigned j0 = g_colptr[c], j1 = g_colptr[c + 1];
    // pass 1: accumulate total (each 8-lane group reads one 128B line per edge)
    for (unsigned j = j0; j < j1; j++) {
        unsigned u = g_colent[j];
        int be = (int)(u >> 10);
        int sh = (int)(u & 1023u);
        int ic = i - sh; if (ic < 0) ic += Zl;
        float4 t = __ldg(&g_msg[(be * Zl + ic) * B4 + b4]);
        acc.x += t.x; acc.y += t.y; acc.z += t.z; acc.w += t.w;
    }
    // pass 2: reload (L1-hot) and overwrite with extrinsic VN->CN messages
    for (unsigned j = j0; j < j1; j++) {
        unsigned u = g_colent[j];
        int be = (int)(u >> 10);
        int sh = (int)(u & 1023u);
        int ic = i - sh; if (ic < 0) ic += Zl;
        int idx = (be * Zl + ic) * B4 + b4;
        float4 t = __ldg(&g_msg[idx]);
        g_msg[idx] = make_float4(acc.x - t.x, acc.y - t.y,
                                 acc.z - t.z, acc.w - t.w);
    }
}

// ---------------- fused finale: final VN total + transpose + negate ---------
// Per chain: computes x = lch + sum(m_cv) for info vars only and writes
// out[b*KI+n] = -x directly (identical fp32 sum order to k_vn pass 1).
__global__ void k_fin(int ofs, float* __restrict__ out) {
    __shared__ float tile[32][33];
    int n0 = blockIdx.x * 32;                    // KI/32 = 264 blocks
    int tx = threadIdx.x, ty = threadIdx.y;      // block (32, 8)
    int v  = n0 + tx;                            // info var (< KI)
    int b4 = ofs + ty;                           // chain's float4 slot
    int c  = v / Zl;
    int i  = v - c * Zl;
    float4 acc = g_lch[v * B4 + b4];
    unsigned j0 = g_colptr[c], j1 = g_colptr[c + 1];
    for (unsigned j = j0; j < j1; j++) {
        unsigned u = g_colent[j];
        int be = (int)(u >> 10);
        int sh = (int)(u & 1023u);
        int ic = i - sh; if (ic < 0) ic += Zl;
        float4 t = __ldg(&g_msg[(be * Zl + ic) * B4 + b4]);
        acc.x += t.x; acc.y += t.y; acc.z += t.z; acc.w += t.w;
    }
    tile[4*ty + 0][tx] = acc.x;
    tile[4*ty + 1][tx] = acc.y;
    tile[4*ty + 2][tx] = acc.z;
    tile[4*ty + 3][tx] = acc.w;
    __syncthreads();
    int bbase = 4 * ofs;                         // chain's first batch element
#pragma unroll
    for (int k = 0; k < 4; k++) {
        int bl = ty + 8 * k;
        out[(size_t)(bbase + bl) * KI + n0 + tx] = -tile[bl][tx];
    }
}

// ---------------- launch: four independent batch chains on forked streams ---
static void run_chain(cudaStream_t s, int ofs, const float* llr, float* out) {
    // per-chain channel slice (transpose 32 batch rows + zero punctured slice)
    {
        dim3 g(NIN / 32 + 6), b(32, 8);
        k_lch<<<g, b, 0, s>>>(llr, ofs);
    }
    k_cn<true, false><<<(MCK * B4Q) / 256, 256, 0, s>>>(ofs);
    k_vn<<<(NLD * B4Q) / 256, 256, 0, s>>>(ofs);
    for (int it = 1; it < NITER - 1; it++) {
        k_cn<false, false><<<(MCK * B4Q) / 256, 256, 0, s>>>(ofs);
        k_vn<<<(NLD * B4Q) / 256, 256, 0, s>>>(ofs);
    }
    k_cn<false, true><<<(MCK * B4Q) / 256, 256, 0, s>>>(ofs);
    // fused finale: final totals for info vars -> transpose -> d_out
    {
        dim3 g(KI / 32), b(32, 8);
        k_fin<<<g, b, 0, s>>>(ofs, out);
    }
}

extern "C" void kernel_launch(void* const* d_in, const int* in_sizes, int n_in,
                              void* d_out, int out_size) {
    const float* llr = (const float*)d_in[0];
    const int*   col = (const int*)d_in[2];
    float*       out = (float*)d_out;

    // host-side infra objects, created once on the (non-captured) first call
    static cudaStream_t st[NCH - 1] = {0, 0, 0};
    static cudaEvent_t  evBld = 0;
    static cudaEvent_t  evJoin[NCH - 1] = {0, 0, 0};
    static bool tried = false, ok = false;
    if (!tried) {
        tried = true;
        ok = true;
        for (int k = 0; k < NCH - 1; k++)
            if (cudaStreamCreateWithFlags(&st[k], cudaStreamNonBlocking) != cudaSuccess) ok = false;
        if (cudaEventCreateWithFlags(&evBld, cudaEventDisableTiming) != cudaSuccess) ok = false;
        for (int k = 0; k < NCH - 1; k++)
            if (cudaEventCreateWithFlags(&evJoin[k], cudaEventDisableTiming) != cudaSuccess) ok = false;
    }

    if (ok) {
        // graph build first (tiny); chains fork off it. Each chain produces
        // its own lch slice, so no full-batch serialization at the head.
        k_build<<<1, 512>>>(col);
        cudaEventRecord(evBld, 0);
        for (int k = 0; k < NCH - 1; k++)
            cudaStreamWaitEvent(st[k], evBld, 0);
        run_chain(0, 0, llr, out);                     // chain 0 on main stream
        for (int k = 0; k < NCH - 1; k++)
            run_chain(st[k], (k + 1) * B4Q, llr, out); // chains 1..3
        for (int k = 0; k < NCH - 1; k++) {
            cudaEventRecord(evJoin[k], st[k]);
            cudaStreamWaitEvent(0, evJoin[k], 0);
        }
    } else {
        k_build<<<1, 512>>>(col);
        for (int k = 0; k < NCH; k++)
            run_chain(0, k * B4Q, llr, out);
    }
}